// round 1
// baseline (speedup 1.0000x reference)
#include <cuda_runtime.h>
#include <stdint.h>

#define SEQ    2048
#define DMODEL 1024
#define NH     16
#define HDIM   64
#define NB     2
#define MROWS  (NB * SEQ)   // 4096

// Scratch (device globals: no allocation allowed in kernel_launch)
__device__ float g_q[MROWS * DMODEL];
__device__ float g_k[MROWS * DMODEL];
__device__ float g_v[MROWS * DMODEL];
__device__ float g_attn[MROWS * DMODEL];

// ---------------------------------------------------------------------------
// C[m][n] = sum_k A[m][k] * W[n][k] + bias[n]
// Tiles: BM=BN=64, BK=16. 256 threads, 4x4 per thread.
// Smem operands stored k-major (transposed) for conflict-free float4 reads.
// ---------------------------------------------------------------------------
__global__ __launch_bounds__(256) void gemm_bias_kernel(
    const float* __restrict__ A, const float* __restrict__ W,
    const float* __restrict__ bias, float* __restrict__ C,
    int M, int N, int K)
{
    __shared__ float As[16 * 64];   // [k][m]
    __shared__ float Ws[16 * 64];   // [k][n]
    const int tid = threadIdx.x;
    const int tx = tid & 15, ty = tid >> 4;
    const int m0 = blockIdx.y << 6, n0 = blockIdx.x << 6;
    const int lrow = tid >> 2;          // 0..63
    const int lc   = (tid & 3) << 2;    // 0,4,8,12

    const float* Ap = A + (size_t)(m0 + lrow) * K + lc;
    const float* Wp = W + (size_t)(n0 + lrow) * K + lc;

    float acc[4][4];
#pragma unroll
    for (int r = 0; r < 4; r++)
#pragma unroll
        for (int c = 0; c < 4; c++) acc[r][c] = 0.f;

    for (int k0 = 0; k0 < K; k0 += 16) {
        float4 av = *(const float4*)(Ap + k0);
        float4 wv = *(const float4*)(Wp + k0);
        As[(lc + 0) * 64 + lrow] = av.x;
        As[(lc + 1) * 64 + lrow] = av.y;
        As[(lc + 2) * 64 + lrow] = av.z;
        As[(lc + 3) * 64 + lrow] = av.w;
        Ws[(lc + 0) * 64 + lrow] = wv.x;
        Ws[(lc + 1) * 64 + lrow] = wv.y;
        Ws[(lc + 2) * 64 + lrow] = wv.z;
        Ws[(lc + 3) * 64 + lrow] = wv.w;
        __syncthreads();
#pragma unroll
        for (int kk = 0; kk < 16; kk++) {
            float4 a = *(const float4*)(As + kk * 64 + ty * 4);
            float4 b = *(const float4*)(Ws + kk * 64 + tx * 4);
            acc[0][0] += a.x * b.x; acc[0][1] += a.x * b.y; acc[0][2] += a.x * b.z; acc[0][3] += a.x * b.w;
            acc[1][0] += a.y * b.x; acc[1][1] += a.y * b.y; acc[1][2] += a.y * b.z; acc[1][3] += a.y * b.w;
            acc[2][0] += a.z * b.x; acc[2][1] += a.z * b.y; acc[2][2] += a.z * b.z; acc[2][3] += a.z * b.w;
            acc[3][0] += a.w * b.x; acc[3][1] += a.w * b.y; acc[3][2] += a.w * b.z; acc[3][3] += a.w * b.w;
        }
        __syncthreads();
    }

    float4 bv = *(const float4*)(bias + n0 + tx * 4);
#pragma unroll
    for (int r = 0; r < 4; r++) {
        int m = m0 + ty * 4 + r;
        float4 ov = make_float4(acc[r][0] + bv.x, acc[r][1] + bv.y,
                                acc[r][2] + bv.z, acc[r][3] + bv.w);
        *(float4*)(C + (size_t)m * N + n0 + tx * 4) = ov;
    }
}

// ---------------------------------------------------------------------------
// Causal flash attention, fp32. 64 queries x 64 keys per block step.
// 256 threads: 16x16 layout, 4x4 microtiles of S and O per thread.
// Smem: QsT [d][qm], KsT [d][key] (reused as P tile), Vs [key][d]. 48KB.
// ---------------------------------------------------------------------------
__global__ __launch_bounds__(256) void attn_kernel(
    const float* __restrict__ Q, const float* __restrict__ Km,
    const float* __restrict__ V, float* __restrict__ O)
{
    __shared__ float QsT[64 * 64];
    __shared__ float KsT[64 * 64];   // reused as Ps after S compute
    __shared__ float Vs[64 * 64];

    const int tid = threadIdx.x;
    const int tx = tid & 15, ty = tid >> 4;
    const int mt = blockIdx.x;               // query tile (0..31)
    const int bh = blockIdx.z;               // b*NH + h
    const int b = bh >> 4, h = bh & 15;
    const int m0 = mt * 64;
    const int hc = h * HDIM;
    const int base = b * SEQ;

    // Load Q tile, transposed into [d][qm]
#pragma unroll
    for (int i = 0; i < 4; i++) {
        int qm = i * 16 + ty;
        float4 qv = *(const float4*)(Q + (size_t)(base + m0 + qm) * DMODEL + hc + tx * 4);
        QsT[(tx * 4 + 0) * 64 + qm] = qv.x;
        QsT[(tx * 4 + 1) * 64 + qm] = qv.y;
        QsT[(tx * 4 + 2) * 64 + qm] = qv.z;
        QsT[(tx * 4 + 3) * 64 + qm] = qv.w;
    }

    float mi[4], li[4], o[4][4];
#pragma unroll
    for (int r = 0; r < 4; r++) {
        mi[r] = -1e30f;
        li[r] = 0.f;
#pragma unroll
        for (int c = 0; c < 4; c++) o[r][c] = 0.f;
    }

    const float scale = 0.125f;   // 1/sqrt(64)

    for (int j = 0; j <= mt; j++) {
        const int n0 = j * 64;
        // Load K (transposed) and V tiles
#pragma unroll
        for (int i = 0; i < 4; i++) {
            int kr = i * 16 + ty;
            float4 kv = *(const float4*)(Km + (size_t)(base + n0 + kr) * DMODEL + hc + tx * 4);
            KsT[(tx * 4 + 0) * 64 + kr] = kv.x;
            KsT[(tx * 4 + 1) * 64 + kr] = kv.y;
            KsT[(tx * 4 + 2) * 64 + kr] = kv.z;
            KsT[(tx * 4 + 3) * 64 + kr] = kv.w;
            float4 vv = *(const float4*)(V + (size_t)(base + n0 + kr) * DMODEL + hc + tx * 4);
            *(float4*)(Vs + kr * 64 + tx * 4) = vv;
        }
        __syncthreads();

        // S = Q K^T
        float s[4][4];
#pragma unroll
        for (int r = 0; r < 4; r++)
#pragma unroll
            for (int c = 0; c < 4; c++) s[r][c] = 0.f;

#pragma unroll 8
        for (int kk = 0; kk < 64; kk++) {
            float4 a = *(const float4*)(QsT + kk * 64 + ty * 4);
            float4 bb = *(const float4*)(KsT + kk * 64 + tx * 4);
            s[0][0] += a.x * bb.x; s[0][1] += a.x * bb.y; s[0][2] += a.x * bb.z; s[0][3] += a.x * bb.w;
            s[1][0] += a.y * bb.x; s[1][1] += a.y * bb.y; s[1][2] += a.y * bb.z; s[1][3] += a.y * bb.w;
            s[2][0] += a.z * bb.x; s[2][1] += a.z * bb.y; s[2][2] += a.z * bb.z; s[2][3] += a.z * bb.w;
            s[3][0] += a.w * bb.x; s[3][1] += a.w * bb.y; s[3][2] += a.w * bb.z; s[3][3] += a.w * bb.w;
        }
        __syncthreads();   // KsT dead; about to be reused as Ps

        // scale + causal mask + online softmax
#pragma unroll
        for (int r = 0; r < 4; r++) {
            const int qrow = m0 + ty * 4 + r;
#pragma unroll
            for (int c = 0; c < 4; c++) {
                float sv = s[r][c] * scale;
                if (n0 + tx * 4 + c > qrow) sv = -1e30f;
                s[r][c] = sv;
            }
            float rm = fmaxf(fmaxf(s[r][0], s[r][1]), fmaxf(s[r][2], s[r][3]));
            rm = fmaxf(rm, __shfl_xor_sync(0xffffffffu, rm, 8));
            rm = fmaxf(rm, __shfl_xor_sync(0xffffffffu, rm, 4));
            rm = fmaxf(rm, __shfl_xor_sync(0xffffffffu, rm, 2));
            rm = fmaxf(rm, __shfl_xor_sync(0xffffffffu, rm, 1));
            float mnew = fmaxf(mi[r], rm);
            float alpha = __expf(mi[r] - mnew);
            mi[r] = mnew;
            float rs = 0.f;
#pragma unroll
            for (int c = 0; c < 4; c++) {
                float p = __expf(s[r][c] - mnew);
                s[r][c] = p;
                rs += p;
            }
            rs += __shfl_xor_sync(0xffffffffu, rs, 8);
            rs += __shfl_xor_sync(0xffffffffu, rs, 4);
            rs += __shfl_xor_sync(0xffffffffu, rs, 2);
            rs += __shfl_xor_sync(0xffffffffu, rs, 1);
            li[r] = li[r] * alpha + rs;
#pragma unroll
            for (int c = 0; c < 4; c++) o[r][c] *= alpha;
        }

        // Store P tile into KsT region
#pragma unroll
        for (int r = 0; r < 4; r++) {
            float4 pv = make_float4(s[r][0], s[r][1], s[r][2], s[r][3]);
            *(float4*)(KsT + (ty * 4 + r) * 64 + tx * 4) = pv;
        }
        __syncthreads();

        // O += P V
#pragma unroll 8
        for (int t = 0; t < 64; t++) {
            float4 vv = *(const float4*)(Vs + t * 64 + tx * 4);
#pragma unroll
            for (int r = 0; r < 4; r++) {
                float p = KsT[(ty * 4 + r) * 64 + t];
                o[r][0] += p * vv.x;
                o[r][1] += p * vv.y;
                o[r][2] += p * vv.z;
                o[r][3] += p * vv.w;
            }
        }
        __syncthreads();   // before next tile overwrites KsT/Vs
    }

    // Normalize and write out in [B,S,(h d)] layout
#pragma unroll
    for (int r = 0; r < 4; r++) {
        int row = m0 + ty * 4 + r;
        float inv = 1.f / li[r];
        float4 ov = make_float4(o[r][0] * inv, o[r][1] * inv,
                                o[r][2] * inv, o[r][3] * inv);
        *(float4*)(O + (size_t)(base + row) * DMODEL + hc + tx * 4) = ov;
    }
}

// ---------------------------------------------------------------------------
extern "C" void kernel_launch(void* const* d_in, const int* in_sizes, int n_in,
                              void* d_out, int out_size)
{
    const float* X  = (const float*)d_in[0];
    const float* Wq = (const float*)d_in[1];
    const float* bq = (const float*)d_in[2];
    const float* Wk = (const float*)d_in[3];
    const float* bk = (const float*)d_in[4];
    const float* Wv = (const float*)d_in[5];
    const float* bv = (const float*)d_in[6];
    const float* Wo = (const float*)d_in[7];
    const float* bo = (const float*)d_in[8];
    float* Y = (float*)d_out;

    float *q, *k, *v, *a;
    cudaGetSymbolAddress((void**)&q, g_q);
    cudaGetSymbolAddress((void**)&k, g_k);
    cudaGetSymbolAddress((void**)&v, g_v);
    cudaGetSymbolAddress((void**)&a, g_attn);

    dim3 gproj(DMODEL / 64, MROWS / 64);   // (16, 64)
    gemm_bias_kernel<<<gproj, 256>>>(X, Wq, bq, q, MROWS, DMODEL, DMODEL);
    gemm_bias_kernel<<<gproj, 256>>>(X, Wk, bk, k, MROWS, DMODEL, DMODEL);
    gemm_bias_kernel<<<gproj, 256>>>(X, Wv, bv, v, MROWS, DMODEL, DMODEL);

    dim3 gattn(SEQ / 64, 1, NB * NH);      // (32, 1, 32)
    attn_kernel<<<gattn, 256>>>(q, k, v, a);

    gemm_bias_kernel<<<gproj, 256>>>(a, Wo, bo, Y, MROWS, DMODEL, DMODEL);
}